// round 3
// baseline (speedup 1.0000x reference)
#include <cuda_runtime.h>
#include <math.h>

// Problem constants
#define BATCH 8
#define TLEN 512
#define SLEN 512
#define EDIM 512
#define HDIM 1024
#define VDIM 32000
#define NL 6
#define MTOT (BATCH*TLEN)        // 4096
#define SCALE 0.7071067811865476f

// ---------------------------------------------------------------------------
// Scratch: single static device buffer (allocation-free rule).
// ---------------------------------------------------------------------------
__device__ float g_scratch[33570816];

#define OFF_EMB    0LL
#define OFF_XPAD   (OFF_EMB    + 2097152LL)
#define OFF_CONVED (OFF_XPAD   + 4210688LL)
#define OFF_GLU    (OFF_CONVED + 8388608LL)
#define OFF_COMB   (OFF_GLU    + 4194304LL)
#define OFF_ATTN   (OFF_COMB   + 2097152LL)
#define OFF_ATT    (OFF_ATTN   + 2097152LL)
#define OFF_COUT   (OFF_ATT    + 2097152LL)
#define OFF_WT     (OFF_COUT   + 2097152LL)

// ---------------------------------------------------------------------------
// embedded[m,:] = tok_emb[trg[m],:] + pos_emb[t,:]
// ---------------------------------------------------------------------------
__global__ void embed_kernel(const int* __restrict__ trg,
                             const float* __restrict__ tok,
                             const float* __restrict__ pos,
                             float* __restrict__ out) {
    int m = blockIdx.x;
    int t = m & (TLEN - 1);
    long long tokid = trg[m];
    const float4* te = (const float4*)(tok + tokid * EDIM);
    const float4* pe = (const float4*)(pos + (long long)t * EDIM);
    float4* o = (float4*)(out + (long long)m * EDIM);
    int i = threadIdx.x;  // 128 threads, EDIM/4 = 128
    float4 a = te[i], b = pe[i];
    o[i] = make_float4(a.x + b.x, a.y + b.y, a.z + b.z, a.w + b.w);
}

// Pad rows (t'=0,1 per batch) = 1.0f  (module quirk: pads with trg_pad_idx)
__global__ void pad_kernel(float* __restrict__ xpad) {
    int i = blockIdx.x * blockDim.x + threadIdx.x;  // 8*2*1024 = 16384
    int b = i >> 11;
    int r = i & 2047;
    xpad[(long long)b * 514 * 1024 + r] = 1.0f;
}

// conv_w[l]: (2H, H, K) -> wt: (K*H, 2H) with wt[kk*H+i][o] = w[o][i][kk]
// smem-tiled transpose: read coalesced over ik, write coalesced over o.
// FIX(R1): write must read the TRANSPOSED tile element tile[tx][r]
// (tile rows = o-offset, cols = ik-offset).
__global__ void transw_kernel(const float* __restrict__ w, float* __restrict__ wt) {
    __shared__ float tile[32][33];
    int ik0 = blockIdx.x * 32;  // over i*3+kk (3072)
    int o0  = blockIdx.y * 32;  // over o     (2048)
    for (int r = threadIdx.y; r < 32; r += 8)
        tile[r][threadIdx.x] = w[(long long)(o0 + r) * 3072 + ik0 + threadIdx.x];
    __syncthreads();
    for (int r = threadIdx.y; r < 32; r += 8) {
        int ikk = ik0 + r;
        int i = ikk / 3, kk = ikk - i * 3;
        long long kcat = (long long)kk * 1024 + i;
        wt[kcat * 2048 + o0 + threadIdx.x] = tile[threadIdx.x][r];
    }
}

// GLU: out[m,j] = conved[m,j] * sigmoid(conved[m,1024+j])
__global__ void glu_kernel(const float* __restrict__ conved, float* __restrict__ out) {
    long long idx = (long long)blockIdx.x * blockDim.x + threadIdx.x;  // 4,194,304
    long long m = idx >> 10;
    int j = (int)(idx & 1023);
    float a = conved[m * 2048 + j];
    float g = conved[m * 2048 + 1024 + j];
    out[idx] = a * (1.0f / (1.0f + expf(-g)));
}

// Row softmax over 512 cols (one block of 128 threads per row, float4 per thread)
__global__ void softmax_kernel(float* __restrict__ attn) {
    long long row = blockIdx.x;
    float4* p = (float4*)(attn + row * 512);
    float4 v = p[threadIdx.x];
    float mx = fmaxf(fmaxf(v.x, v.y), fmaxf(v.z, v.w));
    #pragma unroll
    for (int s = 16; s; s >>= 1) mx = fmaxf(mx, __shfl_xor_sync(0xffffffffu, mx, s));
    __shared__ float sm[4], ss[4];
    int w = threadIdx.x >> 5;
    if ((threadIdx.x & 31) == 0) sm[w] = mx;
    __syncthreads();
    mx = fmaxf(fmaxf(sm[0], sm[1]), fmaxf(sm[2], sm[3]));
    v.x = expf(v.x - mx); v.y = expf(v.y - mx);
    v.z = expf(v.z - mx); v.w = expf(v.w - mx);
    float sum = v.x + v.y + v.z + v.w;
    #pragma unroll
    for (int s = 16; s; s >>= 1) sum += __shfl_xor_sync(0xffffffffu, sum, s);
    if ((threadIdx.x & 31) == 0) ss[w] = sum;
    __syncthreads();
    float inv = 1.0f / (ss[0] + ss[1] + ss[2] + ss[3]);
    v.x *= inv; v.y *= inv; v.z *= inv; v.w *= inv;
    p[threadIdx.x] = v;
}

// ---------------------------------------------------------------------------
// Generic tiled fp32 GEMM: C = epi(A @ B)
//   128x128 block tile, BK=8, 256 threads, 8x8 per-thread microtile.
//   AMAP: 0 = A row m at m*lda
//         1 = xpad conv map   (row base (m+2b)*H, 3072 contiguous = tokens t-2..t)
//         2 = xpad token map  (row base (m+2b+2)*H)
//   CMAP: 0 = C row m at m*N ; 1 = xpad interior map ((m+2b+2)*H)
//   EPI : 0 = +bias
//         1 = (acc + bias + add1[m,n]) * SCALE                      (combined)
//         2 = ((acc + bias + add1[m,n]) * SCALE + C_old) * SCALE    (residual->xpad)
//         3 = plain store
//   BTRANS: B operand is (N x K) row-major, K contiguous (A @ B^T)
// ---------------------------------------------------------------------------
template<int AMAP, int CMAP, int EPI, bool BTRANS>
__global__ __launch_bounds__(256) void gemm128(
    const float* __restrict__ A, const float* __restrict__ Bm,
    const float* __restrict__ bias, const float* __restrict__ add1,
    float* __restrict__ C, int M, int N, int Kd, int lda, int ldb,
    long long batA, long long batB, long long batC)
{
    A  += (long long)blockIdx.z * batA;
    Bm += (long long)blockIdx.z * batB;
    C  += (long long)blockIdx.z * batC;

    __shared__ float As[8][128];
    __shared__ float Bs[8][128];
    const int tid = threadIdx.x;
    const int m0 = blockIdx.y * 128, n0 = blockIdx.x * 128;

    const int a_m  = tid >> 1;
    const int a_k4 = (tid & 1) * 4;
    const int b_k  = tid >> 5;
    const int b_n4 = (tid & 31) * 4;

    const int am = m0 + a_m;
    long long arow;
    if (AMAP == 0)      arow = (long long)am * lda;
    else if (AMAP == 1) arow = (long long)(am + 2 * (am >> 9)) * HDIM;
    else                arow = (long long)(am + 2 * (am >> 9) + 2) * HDIM;

    long long brow;
    if (!BTRANS) brow = (long long)b_k * ldb + n0 + b_n4;
    else         brow = (long long)(n0 + a_m) * ldb + a_k4;

    float acc[8][8];
    #pragma unroll
    for (int i = 0; i < 8; i++)
        #pragma unroll
        for (int j = 0; j < 8; j++) acc[i][j] = 0.0f;

    const int tm = (tid >> 4) * 8;
    const int tn = (tid & 15) * 8;

    for (int k0 = 0; k0 < Kd; k0 += 8) {
        float4 av = *(const float4*)(A + arow + k0 + a_k4);
        float4 bv;
        if (!BTRANS) bv = *(const float4*)(Bm + brow + (long long)k0 * ldb);
        else         bv = *(const float4*)(Bm + brow + k0);
        __syncthreads();
        As[a_k4 + 0][a_m] = av.x;
        As[a_k4 + 1][a_m] = av.y;
        As[a_k4 + 2][a_m] = av.z;
        As[a_k4 + 3][a_m] = av.w;
        if (!BTRANS) {
            *(float4*)(&Bs[b_k][b_n4]) = bv;
        } else {
            Bs[a_k4 + 0][a_m] = bv.x;
            Bs[a_k4 + 1][a_m] = bv.y;
            Bs[a_k4 + 2][a_m] = bv.z;
            Bs[a_k4 + 3][a_m] = bv.w;
        }
        __syncthreads();
        #pragma unroll
        for (int kk = 0; kk < 8; kk++) {
            float af[8], bf[8];
            *(float4*)(af)     = *(const float4*)(&As[kk][tm]);
            *(float4*)(af + 4) = *(const float4*)(&As[kk][tm + 4]);
            *(float4*)(bf)     = *(const float4*)(&Bs[kk][tn]);
            *(float4*)(bf + 4) = *(const float4*)(&Bs[kk][tn + 4]);
            #pragma unroll
            for (int i = 0; i < 8; i++)
                #pragma unroll
                for (int j = 0; j < 8; j++)
                    acc[i][j] = fmaf(af[i], bf[j], acc[i][j]);
        }
    }

    #pragma unroll
    for (int i = 0; i < 8; i++) {
        int m = m0 + tm + i;
        long long coff;
        if (CMAP == 0) coff = (long long)m * N + n0 + tn;
        else           coff = (long long)(m + 2 * (m >> 9) + 2) * HDIM + n0 + tn;
        #pragma unroll
        for (int j = 0; j < 8; j++) {
            float v = acc[i][j];
            int n = n0 + tn + j;
            if (EPI == 0)      v += bias[n];
            else if (EPI == 1) v = (v + bias[n] + add1[(long long)m * N + n]) * SCALE;
            else if (EPI == 2) v = ((v + bias[n] + add1[(long long)m * N + n]) * SCALE
                                    + C[coff + j]) * SCALE;
            C[coff + j] = v;
        }
    }
}

// ---------------------------------------------------------------------------
extern "C" void kernel_launch(void* const* d_in, const int* in_sizes, int n_in,
                              void* d_out, int out_size) {
    const int*   trg         = (const int*)d_in[0];
    const float* enc_conved  = (const float*)d_in[1];
    const float* enc_comb    = (const float*)d_in[2];
    const float* tok_emb     = (const float*)d_in[3];
    const float* pos_emb     = (const float*)d_in[4];
    const float* emb2hid_w   = (const float*)d_in[5];
    const float* emb2hid_b   = (const float*)d_in[6];
    const float* hid2emb_w   = (const float*)d_in[7];
    const float* hid2emb_b   = (const float*)d_in[8];
    const float* attn_h2e_w  = (const float*)d_in[9];
    const float* attn_h2e_b  = (const float*)d_in[10];
    const float* attn_e2h_w  = (const float*)d_in[11];
    const float* attn_e2h_b  = (const float*)d_in[12];
    const float* fc_w        = (const float*)d_in[13];
    const float* fc_b        = (const float*)d_in[14];
    const float* conv_w      = (const float*)d_in[15];
    const float* conv_b      = (const float*)d_in[16];
    float* out = (float*)d_out;

    float* S = nullptr;
    cudaGetSymbolAddress((void**)&S, g_scratch);
    float* emb    = S + OFF_EMB;
    float* xpad   = S + OFF_XPAD;
    float* conved = S + OFF_CONVED;
    float* glu    = S + OFF_GLU;
    float* comb   = S + OFF_COMB;
    float* attn   = S + OFF_ATTN;
    float* att    = S + OFF_ATT;
    float* cout_  = S + OFF_COUT;
    float* wt     = S + OFF_WT;

    const long long TE = (long long)TLEN * EDIM;   // 262144
    const long long TS = (long long)TLEN * SLEN;   // 262144

    // embeddings + pad rows
    embed_kernel<<<MTOT, 128>>>(trg, tok_emb, pos_emb, emb);
    pad_kernel<<<16, 1024>>>(xpad);

    // conv_input = embedded @ emb2hid_w + b   -> xpad interior (token rows)
    gemm128<0, 1, 0, false><<<dim3(8, 32, 1), 256>>>(
        emb, emb2hid_w, emb2hid_b, nullptr, xpad,
        MTOT, HDIM, EDIM, EDIM, HDIM, 0, 0, 0);

    for (int l = 0; l < NL; l++) {
        // permute conv weights: (2H,H,K) -> (3H, 2H)
        transw_kernel<<<dim3(96, 64), dim3(32, 8)>>>(
            conv_w + (long long)l * 2048 * 1024 * 3, wt);

        // conv as GEMM: A rows = 3 consecutive padded token rows (3072 contiguous)
        gemm128<1, 0, 0, false><<<dim3(16, 32, 1), 256>>>(
            xpad, wt, conv_b + l * 2048, nullptr, conved,
            MTOT, 2 * HDIM, 3 * HDIM, HDIM, 2 * HDIM, 0, 0, 0);

        // GLU
        glu_kernel<<<4096, 1024>>>(conved, glu);

        // combined = (glu @ attn_hid2emb_w + b + embedded) * scale
        gemm128<0, 0, 1, false><<<dim3(4, 32, 1), 256>>>(
            glu, attn_h2e_w, attn_h2e_b, emb, comb,
            MTOT, EDIM, HDIM, HDIM, EDIM, 0, 0, 0);

        // energy = combined @ enc_conved^T  (batched NT)
        gemm128<0, 0, 3, true><<<dim3(4, 4, BATCH), 256>>>(
            comb, enc_conved, nullptr, nullptr, attn,
            TLEN, SLEN, EDIM, EDIM, EDIM, TE, TE, TS);

        softmax_kernel<<<MTOT, 128>>>(attn);

        // attended = attn @ enc_combined  (batched NN)
        gemm128<0, 0, 3, false><<<dim3(4, 4, BATCH), 256>>>(
            attn, enc_comb, nullptr, nullptr, att,
            TLEN, EDIM, SLEN, SLEN, EDIM, TS, TE, TE);

        // conv_input = ((glu + attended@W + b)*scale + conv_input)*scale -> xpad
        gemm128<0, 1, 2, false><<<dim3(8, 32, 1), 256>>>(
            att, attn_e2h_w, attn_e2h_b, glu, xpad,
            MTOT, HDIM, EDIM, EDIM, HDIM, 0, 0, 0);
    }

    // conv_output = conv_input @ hid2emb_w + b
    gemm128<2, 0, 0, false><<<dim3(4, 32, 1), 256>>>(
        xpad, hid2emb_w, hid2emb_b, nullptr, cout_,
        MTOT, EDIM, HDIM, HDIM, EDIM, 0, 0, 0);

    // logits = conv_output @ fc_out_w + b
    gemm128<0, 0, 0, false><<<dim3(250, 32, 1), 256>>>(
        cout_, fc_w, fc_b, nullptr, out,
        MTOT, VDIM, EDIM, EDIM, VDIM, 0, 0, 0);
}